// round 1
// baseline (speedup 1.0000x reference)
#include <cuda_runtime.h>
#include <math.h>

#define BB   4
#define SS   1024
#define HIDN 768
#define AHN  384
#define NH   6
#define DDIM 64
#define KSZ  9
#define RPAD 4
#define NROWS (BB*SS)   /* 4096 */

// ---------------- scratch (static device globals: allocation-free) ----------
__device__ float g_mq [NROWS*AHN];
__device__ float g_mk [NROWS*AHN];
__device__ float g_mv [NROWS*AHN];
__device__ float g_co [NROWS*AHN];
__device__ float g_dw [NROWS*HIDN];
__device__ float g_mkc[NROWS*AHN];
__device__ float g_ca [NROWS*AHN];
__device__ float g_ck [NROWS*NH*KSZ];
__device__ float g_tdsm[BB*SS];

// ---------------- generic tiled SGEMM: C = A(MxK) * B + bias ----------------
// BT=false: B stored (K,N) row-major.  BT=true: B stored (N,K) row-major.
template<bool BT, bool BIAS>
__global__ void sgemm(const float* __restrict__ A, const float* __restrict__ Bm,
                      const float* __restrict__ bias, float* __restrict__ C,
                      int M, int N, int K) {
    __shared__ float As[16][64];
    __shared__ float Bs[16][64];
    const int tid = threadIdx.x;
    const int tx = tid & 15, ty = tid >> 4;
    const int bm = blockIdx.y * 64, bn = blockIdx.x * 64;
    float acc[4][4] = {};
    for (int k0 = 0; k0 < K; k0 += 16) {
#pragma unroll
        for (int l = 0; l < 4; l++) {
            int idx = tid + l * 256;
            int m = idx >> 4, k = idx & 15;
            As[k][m] = A[(size_t)(bm + m) * K + (k0 + k)];   // M,K always tile-aligned here
        }
#pragma unroll
        for (int l = 0; l < 4; l++) {
            int idx = tid + l * 256;
            if (BT) {
                int n = idx >> 4, k = idx & 15;
                Bs[k][n] = (bn + n < N) ? Bm[(size_t)(bn + n) * K + (k0 + k)] : 0.f;
            } else {
                int k = idx >> 6, n = idx & 63;
                Bs[k][n] = (bn + n < N) ? Bm[(size_t)(k0 + k) * N + (bn + n)] : 0.f;
            }
        }
        __syncthreads();
#pragma unroll
        for (int k = 0; k < 16; k++) {
            float a[4], bv[4];
#pragma unroll
            for (int u = 0; u < 4; u++) a[u]  = As[k][ty * 4 + u];
#pragma unroll
            for (int v = 0; v < 4; v++) bv[v] = Bs[k][tx * 4 + v];
#pragma unroll
            for (int u = 0; u < 4; u++)
#pragma unroll
                for (int v = 0; v < 4; v++) acc[u][v] += a[u] * bv[v];
        }
        __syncthreads();
    }
#pragma unroll
    for (int u = 0; u < 4; u++) {
        int m = bm + ty * 4 + u;
#pragma unroll
        for (int v = 0; v < 4; v++) {
            int n = bn + tx * 4 + v;
            if (n < N) C[(size_t)m * N + n] = acc[u][v] + (BIAS ? bias[n] : 0.f);
        }
    }
}

// ---------------- depthwise conv over sequence (K input) --------------------
__global__ void dwconv_kernel(const float* __restrict__ Kin,
                              const float* __restrict__ dw_w,
                              float* __restrict__ out) {
    int e = blockIdx.x * 256 + threadIdx.x;
    if (e >= NROWS * HIDN) return;
    int c = e % HIDN;
    int bs = e / HIDN;
    int s = bs % SS, b = bs / SS;
    float acc = 0.f;
#pragma unroll
    for (int t = 0; t < KSZ; t++) {
        int sp = s + t - RPAD;
        if (sp >= 0 && sp < SS)
            acc += Kin[((size_t)b * SS + sp) * HIDN + c] * dw_w[c * KSZ + t];
    }
    out[e] = acc;
}

// ---------------- elementwise multiply --------------------------------------
__global__ void emul_kernel(const float* __restrict__ a, const float* __restrict__ b,
                            float* __restrict__ c, int n) {
    int i = blockIdx.x * 256 + threadIdx.x;
    if (i < n) c[i] = a[i] * b[i];
}

// ---------------- per (b,s,h) softmax over KS kernel taps --------------------
__global__ void ck_softmax_kernel(float* __restrict__ ck) {
    int r = blockIdx.x * 256 + threadIdx.x;
    if (r >= NROWS * NH) return;
    int row = r / NH, h = r % NH;
    float* p = ck + (size_t)row * (NH * KSZ) + h * KSZ;
    float mx = p[0];
#pragma unroll
    for (int t = 1; t < KSZ; t++) mx = fmaxf(mx, p[t]);
    float e[KSZ]; float s = 0.f;
#pragma unroll
    for (int t = 0; t < KSZ; t++) { e[t] = expf(p[t] - mx); s += e[t]; }
    float inv = 1.f / s;
#pragma unroll
    for (int t = 0; t < KSZ; t++) p[t] = e[t] * inv;
}

// ---------------- dynamic-span conv output (second half of out) -------------
__global__ void conv_out_kernel(const float* __restrict__ co,
                                const float* __restrict__ ck,
                                float* __restrict__ out) {
    int r = blockIdx.x;          // (b*S+s)
    int t = threadIdx.x;         // 0..383 = h*64+d
    int h = t >> 6;
    int b = r / SS, s = r % SS;
    __shared__ float cks[NH * KSZ];
    if (t < NH * KSZ) cks[t] = ck[(size_t)r * (NH * KSZ) + t];
    __syncthreads();
    float acc = 0.f;
#pragma unroll
    for (int k = 0; k < KSZ; k++) {
        int sp = s + k - RPAD;
        if (sp >= 0 && sp < SS)
            acc += co[((size_t)b * SS + sp) * AHN + t] * cks[h * KSZ + k];
    }
    out[(size_t)r * 768 + AHN + t] = acc;
}

// ---------------- td softmax (key-mask only: independent of i,h) ------------
__global__ void tdsm_kernel(const float* __restrict__ td, const int* __restrict__ mask,
                            float* __restrict__ out) {
    int b = blockIdx.x;
    int tid = threadIdx.x, lane = tid & 31, wid = tid >> 5;
    __shared__ float buf[SS];
    __shared__ float red[8];
    float ss = 0.f;
    for (int j = tid; j < SS; j += 256) { float v = td[b * SS + j]; ss += v * v; }
#pragma unroll
    for (int o = 16; o > 0; o >>= 1) ss += __shfl_xor_sync(0xffffffffu, ss, o);
    if (lane == 0) red[wid] = ss;
    __syncthreads();
    float tot = 0.f;
#pragma unroll
    for (int w = 0; w < 8; w++) tot += red[w];
    float nrm = fmaxf(sqrtf(tot), 1e-12f);
    __syncthreads();
    float mx = -3.4e38f;
    for (int j = tid; j < SS; j += 256) {
        float v = mask[b * SS + j] ? td[b * SS + j] / nrm : -1e4f;
        buf[j] = v;
        mx = fmaxf(mx, v);
    }
#pragma unroll
    for (int o = 16; o > 0; o >>= 1) mx = fmaxf(mx, __shfl_xor_sync(0xffffffffu, mx, o));
    if (lane == 0) red[wid] = mx;
    __syncthreads();
    float bmx = red[0];
#pragma unroll
    for (int w = 1; w < 8; w++) bmx = fmaxf(bmx, red[w]);
    __syncthreads();
    float sum = 0.f;
    for (int j = tid; j < SS; j += 256) {
        float e = expf(buf[j] - bmx);
        buf[j] = e;
        sum += e;
    }
#pragma unroll
    for (int o = 16; o > 0; o >>= 1) sum += __shfl_xor_sync(0xffffffffu, sum, o);
    if (lane == 0) red[wid] = sum;
    __syncthreads();
    float bsum = 0.f;
#pragma unroll
    for (int w = 0; w < 8; w++) bsum += red[w];
    float inv = 1.f / bsum;
    __syncthreads();
    for (int j = tid; j < SS; j += 256) out[b * SS + j] = buf[j] * inv;
}

// ---------------- attention with monotonic distance decay -------------------
// one block per (b,h,i) query row; 256 threads
__global__ void attn_kernel(const float* __restrict__ mq, const float* __restrict__ mk,
                            const float* __restrict__ mv, const int* __restrict__ mask,
                            const float* __restrict__ tdsm, const float* __restrict__ gammas,
                            float* __restrict__ out) {
    const int i = blockIdx.x, h = blockIdx.y, b = blockIdx.z;
    const int tid = threadIdx.x, lane = tid & 31, wid = tid >> 5;
    __shared__ float sc[SS];      // raw scores, then rescored
    __shared__ float pb[SS];      // p / cumsum / probs
    __shared__ float mf[SS];      // key mask as float
    __shared__ float qv[DDIM];
    __shared__ float red[8];
    __shared__ float scan[256];

    if (tid < DDIM) qv[tid] = mq[((size_t)b * SS + i) * AHN + h * DDIM + tid];
    for (int j = tid; j < SS; j += 256) mf[j] = mask[b * SS + j] ? 1.f : 0.f;
    __syncthreads();

    // ---- raw scores: each warp owns j = wid, wid+8, ... ----
    {
        float q0 = qv[lane], q1 = qv[lane + 32];
        for (int j = wid; j < SS; j += 8) {
            const float* kr = mk + ((size_t)b * SS + j) * AHN + h * DDIM;
            float p = q0 * kr[lane] + q1 * kr[lane + 32];
#pragma unroll
            for (int o = 16; o > 0; o >>= 1) p += __shfl_xor_sync(0xffffffffu, p, o);
            if (lane == 0) sc[j] = p * 0.125f;   // /sqrt(64)
        }
    }
    __syncthreads();

    // ---- softmax #1 over masked scores ----
    float mx = -3.4e38f;
    for (int j = tid; j < SS; j += 256) {
        float v = mf[j] > 0.f ? sc[j] : -1e8f;
        mx = fmaxf(mx, v);
    }
#pragma unroll
    for (int o = 16; o > 0; o >>= 1) mx = fmaxf(mx, __shfl_xor_sync(0xffffffffu, mx, o));
    if (lane == 0) red[wid] = mx;
    __syncthreads();
    float bmx = red[0];
#pragma unroll
    for (int w = 1; w < 8; w++) bmx = fmaxf(bmx, red[w]);
    __syncthreads();
    float sum = 0.f;
    for (int j = tid; j < SS; j += 256) {
        float v = mf[j] > 0.f ? sc[j] : -1e8f;
        float e = expf(v - bmx) * mf[j];
        pb[j] = e;
        sum += e;
    }
#pragma unroll
    for (int o = 16; o > 0; o >>= 1) sum += __shfl_xor_sync(0xffffffffu, sum, o);
    if (lane == 0) red[wid] = sum;
    __syncthreads();
    float bsum = 0.f;
#pragma unroll
    for (int w = 0; w < 8; w++) bsum += red[w];
    float inv = bsum > 0.f ? 1.f / bsum : 0.f;
    __syncthreads();

    // ---- inclusive cumsum of p over j (thread t owns j = 4t..4t+3) ----
    float a0 = pb[4 * tid] * inv;
    float a1 = a0 + pb[4 * tid + 1] * inv;
    float a2 = a1 + pb[4 * tid + 2] * inv;
    float a3 = a2 + pb[4 * tid + 3] * inv;
    scan[tid] = a3;
    __syncthreads();
#pragma unroll
    for (int off = 1; off < 256; off <<= 1) {
        float add = (tid >= off) ? scan[tid - off] : 0.f;
        __syncthreads();
        scan[tid] += add;
        __syncthreads();
    }
    float total = scan[255];
    float excl = scan[tid] - a3;
    pb[4 * tid + 0] = excl + a0;
    pb[4 * tid + 1] = excl + a1;
    pb[4 * tid + 2] = excl + a2;
    pb[4 * tid + 3] = excl + a3;
    __syncthreads();

    // ---- rescore with total_effect ----
    {
        float gm = gammas[h];
        float spv = (gm > 20.f) ? gm : log1pf(expf(gm));
        float gamma = -spv;
        for (int j = tid; j < SS; j += 256) {
            float pos = fabsf((float)(j - i));
            float ds = sqrtf(fmaxf((total - pb[j]) * pos, 0.f));
            float te = fminf(fmaxf(expf(ds * gamma), 1e-5f), 1e5f);
            if (j < i) te -= tdsm[b * SS + j];
            sc[j] = mf[j] > 0.f ? sc[j] * te : -1e8f;
        }
    }
    __syncthreads();

    // ---- softmax #2 (plain) ----
    mx = -3.4e38f;
    for (int j = tid; j < SS; j += 256) mx = fmaxf(mx, sc[j]);
#pragma unroll
    for (int o = 16; o > 0; o >>= 1) mx = fmaxf(mx, __shfl_xor_sync(0xffffffffu, mx, o));
    if (lane == 0) red[wid] = mx;
    __syncthreads();
    float bmx2 = red[0];
#pragma unroll
    for (int w = 1; w < 8; w++) bmx2 = fmaxf(bmx2, red[w]);
    __syncthreads();
    sum = 0.f;
    for (int j = tid; j < SS; j += 256) {
        float e = expf(sc[j] - bmx2);
        pb[j] = e;
        sum += e;
    }
#pragma unroll
    for (int o = 16; o > 0; o >>= 1) sum += __shfl_xor_sync(0xffffffffu, sum, o);
    if (lane == 0) red[wid] = sum;
    __syncthreads();   // pb writes now visible block-wide
    float bsum2 = 0.f;
#pragma unroll
    for (int w = 0; w < 8; w++) bsum2 += red[w];
    float inv2 = 1.f / bsum2;

    // ---- ctx = probs @ V : 4 j-groups x 64 d-lanes ----
    int g4 = tid >> 6, d = tid & 63;
    float acc = 0.f;
    for (int j = g4; j < SS; j += 4)
        acc += pb[j] * mv[((size_t)b * SS + j) * AHN + h * DDIM + d];
    acc *= inv2;
    __syncthreads();
    scan[tid] = acc;
    __syncthreads();
    if (tid < 64) {
        float r = scan[tid] + scan[tid + 64] + scan[tid + 128] + scan[tid + 192];
        out[((size_t)b * SS + i) * 768 + h * DDIM + tid] = r;
    }
}

// ---------------- launch ----------------------------------------------------
extern "C" void kernel_launch(void* const* d_in, const int* in_sizes, int n_in,
                              void* d_out, int out_size) {
    const float* Q    = (const float*)d_in[0];
    const float* Kin  = (const float*)d_in[1];
    const float* V    = (const float*)d_in[2];
    const float* td   = (const float*)d_in[3];
    const int*   mask = (const int*)  d_in[4];
    const float* Wq   = (const float*)d_in[5];
    const float* Wk   = (const float*)d_in[6];
    const float* Wv   = (const float*)d_in[7];
    const float* dw_w = (const float*)d_in[8];
    const float* pw_w = (const float*)d_in[9];
    const float* sep_b= (const float*)d_in[10];
    const float* ck_W = (const float*)d_in[11];
    const float* ck_b = (const float*)d_in[12];
    const float* co_W = (const float*)d_in[13];
    const float* co_b = (const float*)d_in[14];
    const float* gammas=(const float*)d_in[15];
    float* out = (float*)d_out;

    float *mq, *mk, *mv, *co, *dw, *mkc, *ca, *ck, *tdsm;
    cudaGetSymbolAddress((void**)&mq,  g_mq);
    cudaGetSymbolAddress((void**)&mk,  g_mk);
    cudaGetSymbolAddress((void**)&mv,  g_mv);
    cudaGetSymbolAddress((void**)&co,  g_co);
    cudaGetSymbolAddress((void**)&dw,  g_dw);
    cudaGetSymbolAddress((void**)&mkc, g_mkc);
    cudaGetSymbolAddress((void**)&ca,  g_ca);
    cudaGetSymbolAddress((void**)&ck,  g_ck);
    cudaGetSymbolAddress((void**)&tdsm,g_tdsm);

    dim3 gProj(AHN / 64, NROWS / 64);          // (6, 64)
    sgemm<false, false><<<gProj, 256>>>(Q,   Wq,   nullptr, mq,  NROWS, AHN, HIDN);
    sgemm<false, false><<<gProj, 256>>>(Kin, Wk,   nullptr, mk,  NROWS, AHN, HIDN);
    sgemm<false, false><<<gProj, 256>>>(V,   Wv,   nullptr, mv,  NROWS, AHN, HIDN);
    sgemm<false, true ><<<gProj, 256>>>(V,   co_W, co_b,    co,  NROWS, AHN, HIDN);

    dwconv_kernel<<<(NROWS * HIDN + 255) / 256, 256>>>(Kin, dw_w, dw);
    sgemm<true, true><<<gProj, 256>>>(dw, pw_w, sep_b, mkc, NROWS, AHN, HIDN);

    emul_kernel<<<(NROWS * AHN + 255) / 256, 256>>>(mkc, mq, ca, NROWS * AHN);
    sgemm<false, true><<<dim3(1, NROWS / 64), 256>>>(ca, ck_W, ck_b, ck,
                                                     NROWS, NH * KSZ, AHN);
    ck_softmax_kernel<<<(NROWS * NH + 255) / 256, 256>>>(ck);
    conv_out_kernel<<<NROWS, AHN>>>(co, ck, out);

    tdsm_kernel<<<BB, 256>>>(td, mask, tdsm);
    attn_kernel<<<dim3(SS, NH, BB), 256>>>(mq, mk, mv, mask, tdsm, gammas, out);
}

// round 2
// speedup vs baseline: 1.9812x; 1.9812x over previous
#include <cuda_runtime.h>
#include <math.h>

#define BB   4
#define SS   1024
#define HIDN 768
#define AHN  384
#define NH   6
#define DDIM 64
#define KSZ  9
#define RPAD 4
#define NROWS (BB*SS)   /* 4096 */
#define TI   16         /* query rows per attention block */

// ---------------- scratch (static device globals: allocation-free) ----------
__device__ float g_mq [NROWS*AHN];
__device__ float g_mk [NROWS*AHN];
__device__ float g_mv [NROWS*AHN];
__device__ float g_co [NROWS*AHN];
__device__ float g_dw [NROWS*HIDN];
__device__ float g_mkc[NROWS*AHN];
__device__ float g_ca [NROWS*AHN];
__device__ float g_ck [NROWS*NH*KSZ];
__device__ float g_tdsm[BB*SS];

// ---------------- fast SGEMM: 128x64 tile, 8x4 microtile, float4 ------------
// BT=false: B stored (K,N) row-major.  BT=true: B stored (N,K) row-major.
// Requires: M%128==0, N%64==0, K%16==0 (true for all big GEMMs here).
template<bool BT, bool BIAS>
__global__ __launch_bounds__(256)
void sgemm2(const float* __restrict__ A, const float* __restrict__ Bm,
            const float* __restrict__ bias, float* __restrict__ C,
            int M, int N, int K) {
    __shared__ float As[16 * 132];
    __shared__ float Bs[16 * 68];
    const int tid = threadIdx.x;
    const int tx = tid & 15, ty = tid >> 4;
    const int bm = blockIdx.y * 128, bn = blockIdx.x * 64;
    float acc[8][4] = {};
    for (int k0 = 0; k0 < K; k0 += 16) {
#pragma unroll
        for (int l = 0; l < 2; l++) {
            int li = tid + 256 * l;
            int m = li >> 2, kq = li & 3;
            float4 v = *(const float4*)&A[(size_t)(bm + m) * K + k0 + 4 * kq];
            As[(4 * kq + 0) * 132 + m] = v.x;
            As[(4 * kq + 1) * 132 + m] = v.y;
            As[(4 * kq + 2) * 132 + m] = v.z;
            As[(4 * kq + 3) * 132 + m] = v.w;
        }
        if (BT) {
            int n = tid >> 2, kq = tid & 3;
            float4 v = *(const float4*)&Bm[(size_t)(bn + n) * K + k0 + 4 * kq];
            Bs[(4 * kq + 0) * 68 + n] = v.x;
            Bs[(4 * kq + 1) * 68 + n] = v.y;
            Bs[(4 * kq + 2) * 68 + n] = v.z;
            Bs[(4 * kq + 3) * 68 + n] = v.w;
        } else {
            int k = tid >> 4, nq = tid & 15;
            float4 v = *(const float4*)&Bm[(size_t)(k0 + k) * N + bn + 4 * nq];
            *(float4*)&Bs[k * 68 + 4 * nq] = v;
        }
        __syncthreads();
#pragma unroll
        for (int k = 0; k < 16; k++) {
            float4 a0 = *(const float4*)&As[k * 132 + ty * 8];
            float4 a1 = *(const float4*)&As[k * 132 + ty * 8 + 4];
            float4 b0 = *(const float4*)&Bs[k * 68 + tx * 4];
            float av[8] = {a0.x, a0.y, a0.z, a0.w, a1.x, a1.y, a1.z, a1.w};
            float bv[4] = {b0.x, b0.y, b0.z, b0.w};
#pragma unroll
            for (int u = 0; u < 8; u++)
#pragma unroll
                for (int v = 0; v < 4; v++) acc[u][v] += av[u] * bv[v];
        }
        __syncthreads();
    }
    float4 bb = make_float4(0.f, 0.f, 0.f, 0.f);
    if (BIAS) bb = *(const float4*)&bias[bn + tx * 4];
#pragma unroll
    for (int u = 0; u < 8; u++) {
        float4 o;
        o.x = acc[u][0] + bb.x;
        o.y = acc[u][1] + bb.y;
        o.z = acc[u][2] + bb.z;
        o.w = acc[u][3] + bb.w;
        *(float4*)&C[(size_t)(bm + ty * 8 + u) * N + bn + tx * 4] = o;
    }
}

// ---------------- small guarded SGEMM (for N=54 conv-kernel layer) ----------
template<bool BT, bool BIAS>
__global__ void sgemm_small(const float* __restrict__ A, const float* __restrict__ Bm,
                            const float* __restrict__ bias, float* __restrict__ C,
                            int M, int N, int K) {
    __shared__ float As[16][64];
    __shared__ float Bs[16][64];
    const int tid = threadIdx.x;
    const int tx = tid & 15, ty = tid >> 4;
    const int bm = blockIdx.y * 64, bn = blockIdx.x * 64;
    float acc[4][4] = {};
    for (int k0 = 0; k0 < K; k0 += 16) {
#pragma unroll
        for (int l = 0; l < 4; l++) {
            int idx = tid + l * 256;
            int m = idx >> 4, k = idx & 15;
            As[k][m] = A[(size_t)(bm + m) * K + (k0 + k)];
        }
#pragma unroll
        for (int l = 0; l < 4; l++) {
            int idx = tid + l * 256;
            if (BT) {
                int n = idx >> 4, k = idx & 15;
                Bs[k][n] = (bn + n < N) ? Bm[(size_t)(bn + n) * K + (k0 + k)] : 0.f;
            } else {
                int k = idx >> 6, n = idx & 63;
                Bs[k][n] = (bn + n < N) ? Bm[(size_t)(k0 + k) * N + (bn + n)] : 0.f;
            }
        }
        __syncthreads();
#pragma unroll
        for (int k = 0; k < 16; k++) {
            float a[4], bv[4];
#pragma unroll
            for (int u = 0; u < 4; u++) a[u]  = As[k][ty * 4 + u];
#pragma unroll
            for (int v = 0; v < 4; v++) bv[v] = Bs[k][tx * 4 + v];
#pragma unroll
            for (int u = 0; u < 4; u++)
#pragma unroll
                for (int v = 0; v < 4; v++) acc[u][v] += a[u] * bv[v];
        }
        __syncthreads();
    }
#pragma unroll
    for (int u = 0; u < 4; u++) {
        int m = bm + ty * 4 + u;
#pragma unroll
        for (int v = 0; v < 4; v++) {
            int n = bn + tx * 4 + v;
            if (n < N) C[(size_t)m * N + n] = acc[u][v] + (BIAS ? bias[n] : 0.f);
        }
    }
}

// ---------------- depthwise conv over sequence (K input) --------------------
__global__ void dwconv_kernel(const float* __restrict__ Kin,
                              const float* __restrict__ dw_w,
                              float* __restrict__ out) {
    int e = blockIdx.x * 256 + threadIdx.x;
    if (e >= NROWS * HIDN) return;
    int c = e % HIDN;
    int bs = e / HIDN;
    int s = bs % SS, b = bs / SS;
    float acc = 0.f;
#pragma unroll
    for (int t = 0; t < KSZ; t++) {
        int sp = s + t - RPAD;
        if (sp >= 0 && sp < SS)
            acc += Kin[((size_t)b * SS + sp) * HIDN + c] * dw_w[c * KSZ + t];
    }
    out[e] = acc;
}

// ---------------- elementwise multiply --------------------------------------
__global__ void emul_kernel(const float* __restrict__ a, const float* __restrict__ b,
                            float* __restrict__ c, int n) {
    int i = blockIdx.x * 256 + threadIdx.x;
    if (i < n) c[i] = a[i] * b[i];
}

// ---------------- per (b,s,h) softmax over KS kernel taps --------------------
__global__ void ck_softmax_kernel(float* __restrict__ ck) {
    int r = blockIdx.x * 256 + threadIdx.x;
    if (r >= NROWS * NH) return;
    int row = r / NH, h = r % NH;
    float* p = ck + (size_t)row * (NH * KSZ) + h * KSZ;
    float mx = p[0];
#pragma unroll
    for (int t = 1; t < KSZ; t++) mx = fmaxf(mx, p[t]);
    float e[KSZ]; float s = 0.f;
#pragma unroll
    for (int t = 0; t < KSZ; t++) { e[t] = expf(p[t] - mx); s += e[t]; }
    float inv = 1.f / s;
#pragma unroll
    for (int t = 0; t < KSZ; t++) p[t] = e[t] * inv;
}

// ---------------- dynamic-span conv output (second half of out) -------------
__global__ void conv_out_kernel(const float* __restrict__ co,
                                const float* __restrict__ ck,
                                float* __restrict__ out) {
    int r = blockIdx.x;          // (b*S+s)
    int t = threadIdx.x;         // 0..383 = h*64+d
    int h = t >> 6;
    int b = r / SS, s = r % SS;
    __shared__ float cks[NH * KSZ];
    if (t < NH * KSZ) cks[t] = ck[(size_t)r * (NH * KSZ) + t];
    __syncthreads();
    float acc = 0.f;
#pragma unroll
    for (int k = 0; k < KSZ; k++) {
        int sp = s + k - RPAD;
        if (sp >= 0 && sp < SS)
            acc += co[((size_t)b * SS + sp) * AHN + t] * cks[h * KSZ + k];
    }
    out[(size_t)r * 768 + AHN + t] = acc;
}

// ---------------- td softmax (key-mask only: independent of i,h) ------------
__global__ void tdsm_kernel(const float* __restrict__ td, const int* __restrict__ mask,
                            float* __restrict__ out) {
    int b = blockIdx.x;
    int tid = threadIdx.x, lane = tid & 31, wid = tid >> 5;
    __shared__ float buf[SS];
    __shared__ float red[8];
    float ss = 0.f;
    for (int j = tid; j < SS; j += 256) { float v = td[b * SS + j]; ss += v * v; }
#pragma unroll
    for (int o = 16; o > 0; o >>= 1) ss += __shfl_xor_sync(0xffffffffu, ss, o);
    if (lane == 0) red[wid] = ss;
    __syncthreads();
    float tot = 0.f;
#pragma unroll
    for (int w = 0; w < 8; w++) tot += red[w];
    float nrm = fmaxf(sqrtf(tot), 1e-12f);
    __syncthreads();
    float mx = -3.4e38f;
    for (int j = tid; j < SS; j += 256) {
        float v = mask[b * SS + j] ? td[b * SS + j] / nrm : -1e4f;
        buf[j] = v;
        mx = fmaxf(mx, v);
    }
#pragma unroll
    for (int o = 16; o > 0; o >>= 1) mx = fmaxf(mx, __shfl_xor_sync(0xffffffffu, mx, o));
    if (lane == 0) red[wid] = mx;
    __syncthreads();
    float bmx = red[0];
#pragma unroll
    for (int w = 1; w < 8; w++) bmx = fmaxf(bmx, red[w]);
    __syncthreads();
    float sum = 0.f;
    for (int j = tid; j < SS; j += 256) {
        float e = expf(buf[j] - bmx);
        buf[j] = e;
        sum += e;
    }
#pragma unroll
    for (int o = 16; o > 0; o >>= 1) sum += __shfl_xor_sync(0xffffffffu, sum, o);
    if (lane == 0) red[wid] = sum;
    __syncthreads();
    float bsum = 0.f;
#pragma unroll
    for (int w = 0; w < 8; w++) bsum += red[w];
    float inv = 1.f / bsum;
    __syncthreads();
    for (int j = tid; j < SS; j += 256) out[b * SS + j] = buf[j] * inv;
}

// ---------------- attention: 16 query rows per block ------------------------
// block = (i-tile, h, b); 256 threads = 8 warps; warp w owns rows 2w, 2w+1.
// smem: sc[16][1024] scores->probs | Kt[128][68] K/V tile | qs[16][64] | ms[1024]
__global__ __launch_bounds__(256)
void attn_kernel(const float* __restrict__ mq, const float* __restrict__ mk,
                 const float* __restrict__ mv, const int* __restrict__ mask,
                 const float* __restrict__ tdsm, const float* __restrict__ gammas,
                 float* __restrict__ out) {
    extern __shared__ float sm[];
    float* sc = sm;                       // 16*1024
    float* Kt = sm + TI * SS;             // 128*68
    float* qs = Kt + 128 * 68;            // 16*64
    float* ms = qs + TI * DDIM;           // 1024

    const int i0 = blockIdx.x * TI;
    const int h  = blockIdx.y;
    const int b  = blockIdx.z;
    const int tid = threadIdx.x, lane = tid & 31, w = tid >> 5;

    // ---- phase 0: load q rows + mask ----
    {
        int r = tid >> 4, kq = tid & 15;
        const float4* mq4 = (const float4*)mq;
        *(float4*)&qs[r * DDIM + kq * 4] =
            mq4[(size_t)(b * SS + i0 + r) * 96 + h * 16 + kq];
        const int4* m4 = (const int4*)mask;
        int4 mm = m4[(size_t)(b * SS) / 4 + tid];
        ms[4 * tid + 0] = mm.x ? 1.f : 0.f;
        ms[4 * tid + 1] = mm.y ? 1.f : 0.f;
        ms[4 * tid + 2] = mm.z ? 1.f : 0.f;
        ms[4 * tid + 3] = mm.w ? 1.f : 0.f;
    }

    // ---- phase 1: scores sc[r][j] = q.k/8 ----
    const int rg = tid >> 5;      // 0..7 -> rows 2rg, 2rg+1
    const int jg = tid & 31;
    for (int jt = 0; jt < 8; jt++) {
        int j0 = jt * 128;
#pragma unroll
        for (int l = 0; l < 8; l++) {
            int li = tid + 256 * l;
            int j = li >> 4, kq = li & 15;
            float4 v = ((const float4*)mk)[(size_t)(b * SS + j0 + j) * 96 + h * 16 + kq];
            *(float4*)&Kt[j * 68 + kq * 4] = v;
        }
        __syncthreads();
        float acc[2][4] = {};
#pragma unroll
        for (int k = 0; k < DDIM; k += 4) {
            float4 q0 = *(const float4*)&qs[(2 * rg) * DDIM + k];
            float4 q1 = *(const float4*)&qs[(2 * rg + 1) * DDIM + k];
#pragma unroll
            for (int jj = 0; jj < 4; jj++) {
                float4 kv = *(const float4*)&Kt[(jg + 32 * jj) * 68 + k];
                acc[0][jj] += q0.x * kv.x + q0.y * kv.y + q0.z * kv.z + q0.w * kv.w;
                acc[1][jj] += q1.x * kv.x + q1.y * kv.y + q1.z * kv.z + q1.w * kv.w;
            }
        }
#pragma unroll
        for (int rr = 0; rr < 2; rr++)
#pragma unroll
            for (int jj = 0; jj < 4; jj++)
                sc[(2 * rg + rr) * SS + j0 + jg + 32 * jj] = acc[rr][jj] * 0.125f;
        __syncthreads();
    }

    // ---- phase 2: per-row softmax -> cumsum -> rescore -> softmax ----
    float gm = gammas[h];
    float gamma = -((gm > 20.f) ? gm : log1pf(expf(gm)));
#pragma unroll 1
    for (int rr = 0; rr < 2; rr++) {
        int r = 2 * w + rr;
        int i = i0 + r;
        float s[32], p[32];
        // load, apply key mask
#pragma unroll
        for (int t = 0; t < 32; t++) {
            float v = sc[r * SS + t * 32 + lane];
            s[t] = (ms[t * 32 + lane] > 0.f) ? v : -1e8f;
        }
        // softmax #1
        float mx = -3.4e38f;
#pragma unroll
        for (int t = 0; t < 32; t++) mx = fmaxf(mx, s[t]);
#pragma unroll
        for (int o = 16; o > 0; o >>= 1) mx = fmaxf(mx, __shfl_xor_sync(0xffffffffu, mx, o));
        float sum = 0.f;
#pragma unroll
        for (int t = 0; t < 32; t++) { p[t] = expf(s[t] - mx); sum += p[t]; }
#pragma unroll
        for (int o = 16; o > 0; o >>= 1) sum += __shfl_xor_sync(0xffffffffu, sum, o);
        float inv = 1.f / sum;
        // inclusive cumsum over j (j = t*32 + lane ordering)
        float off = 0.f;
#pragma unroll
        for (int t = 0; t < 32; t++) {
            float x = p[t] * inv;
#pragma unroll
            for (int d = 1; d < 32; d <<= 1) {
                float y = __shfl_up_sync(0xffffffffu, x, d);
                if (lane >= d) x += y;
            }
            float cum = x + off;
            off = __shfl_sync(0xffffffffu, cum, 31);
            p[t] = cum;
        }
        float total = off;
        // rescore with distance decay
#pragma unroll
        for (int t = 0; t < 32; t++) {
            int j = t * 32 + lane;
            if (s[t] > -1e7f) {
                float pos = fabsf((float)(j - i));
                float ds = sqrtf(fmaxf((total - p[t]) * pos, 0.f));
                float te = fmaxf(expf(ds * gamma), 1e-5f);
                if (j < i) te -= tdsm[b * SS + j];
                s[t] = s[t] * te;
            }
        }
        // softmax #2
        float mx2 = -3.4e38f;
#pragma unroll
        for (int t = 0; t < 32; t++) mx2 = fmaxf(mx2, s[t]);
#pragma unroll
        for (int o = 16; o > 0; o >>= 1) mx2 = fmaxf(mx2, __shfl_xor_sync(0xffffffffu, mx2, o));
        float sum2 = 0.f;
#pragma unroll
        for (int t = 0; t < 32; t++) { p[t] = expf(s[t] - mx2); sum2 += p[t]; }
#pragma unroll
        for (int o = 16; o > 0; o >>= 1) sum2 += __shfl_xor_sync(0xffffffffu, sum2, o);
        float inv2 = 1.f / sum2;
#pragma unroll
        for (int t = 0; t < 32; t++) sc[r * SS + t * 32 + lane] = p[t] * inv2;
    }

    // ---- phase 3: ctx = probs @ V ----
    const int r0 = 2 * rg, r1 = 2 * rg + 1;
    float a00 = 0.f, a01 = 0.f, a10 = 0.f, a11 = 0.f;
    for (int jt = 0; jt < 8; jt++) {
        int j0 = jt * 128;
#pragma unroll
        for (int l = 0; l < 8; l++) {
            int li = tid + 256 * l;
            int j = li >> 4, kq = li & 15;
            float4 v = ((const float4*)mv)[(size_t)(b * SS + j0 + j) * 96 + h * 16 + kq];
            *(float4*)&Kt[j * 68 + kq * 4] = v;
        }
        __syncthreads();
#pragma unroll 4
        for (int j = 0; j < 128; j += 4) {
            float4 p0 = *(const float4*)&sc[r0 * SS + j0 + j];
            float4 p1 = *(const float4*)&sc[r1 * SS + j0 + j];
            float pp0[4] = {p0.x, p0.y, p0.z, p0.w};
            float pp1[4] = {p1.x, p1.y, p1.z, p1.w};
#pragma unroll
            for (int jj = 0; jj < 4; jj++) {
                float v0 = Kt[(j + jj) * 68 + lane];
                float v1 = Kt[(j + jj) * 68 + lane + 32];
                a00 += pp0[jj] * v0; a01 += pp0[jj] * v1;
                a10 += pp1[jj] * v0; a11 += pp1[jj] * v1;
            }
        }
        __syncthreads();
    }
    {
        size_t o0 = (size_t)(b * SS + i0 + r0) * 768 + h * DDIM;
        size_t o1 = (size_t)(b * SS + i0 + r1) * 768 + h * DDIM;
        out[o0 + lane] = a00; out[o0 + lane + 32] = a01;
        out[o1 + lane] = a10; out[o1 + lane + 32] = a11;
    }
}

// ---------------- launch ----------------------------------------------------
extern "C" void kernel_launch(void* const* d_in, const int* in_sizes, int n_in,
                              void* d_out, int out_size) {
    const float* Q    = (const float*)d_in[0];
    const float* Kin  = (const float*)d_in[1];
    const float* V    = (const float*)d_in[2];
    const float* td   = (const float*)d_in[3];
    const int*   mask = (const int*)  d_in[4];
    const float* Wq   = (const float*)d_in[5];
    const float* Wk   = (const float*)d_in[6];
    const float* Wv   = (const float*)d_in[7];
    const float* dw_w = (const float*)d_in[8];
    const float* pw_w = (const float*)d_in[9];
    const float* sep_b= (const float*)d_in[10];
    const float* ck_W = (const float*)d_in[11];
    const float* ck_b = (const float*)d_in[12];
    const float* co_W = (const float*)d_in[13];
    const float* co_b = (const float*)d_in[14];
    const float* gammas=(const float*)d_in[15];
    float* out = (float*)d_out;

    float *mq, *mk, *mv, *co, *dw, *mkc, *ca, *ck, *tdsm;
    cudaGetSymbolAddress((void**)&mq,  g_mq);
    cudaGetSymbolAddress((void**)&mk,  g_mk);
    cudaGetSymbolAddress((void**)&mv,  g_mv);
    cudaGetSymbolAddress((void**)&co,  g_co);
    cudaGetSymbolAddress((void**)&dw,  g_dw);
    cudaGetSymbolAddress((void**)&mkc, g_mkc);
    cudaGetSymbolAddress((void**)&ca,  g_ca);
    cudaGetSymbolAddress((void**)&ck,  g_ck);
    cudaGetSymbolAddress((void**)&tdsm,g_tdsm);

    static int smem_set = 0;
    const int attn_smem = (TI * SS + 128 * 68 + TI * DDIM + SS) * 4;  // 108544 B
    if (!smem_set) {
        cudaFuncSetAttribute(attn_kernel, cudaFuncAttributeMaxDynamicSharedMemorySize,
                             attn_smem);
        smem_set = 1;
    }

    dim3 gBig(AHN / 64, NROWS / 128);          // (6, 32)
    sgemm2<false, false><<<gBig, 256>>>(Q,   Wq,   nullptr, mq,  NROWS, AHN, HIDN);
    sgemm2<false, false><<<gBig, 256>>>(Kin, Wk,   nullptr, mk,  NROWS, AHN, HIDN);
    sgemm2<false, false><<<gBig, 256>>>(V,   Wv,   nullptr, mv,  NROWS, AHN, HIDN);
    sgemm2<false, true ><<<gBig, 256>>>(V,   co_W, co_b,    co,  NROWS, AHN, HIDN);

    dwconv_kernel<<<(NROWS * HIDN + 255) / 256, 256>>>(Kin, dw_w, dw);
    sgemm2<true, true><<<gBig, 256>>>(dw, pw_w, sep_b, mkc, NROWS, AHN, HIDN);

    emul_kernel<<<(NROWS * AHN + 255) / 256, 256>>>(mkc, mq, ca, NROWS * AHN);
    sgemm_small<false, true><<<dim3(1, NROWS / 64), 256>>>(ca, ck_W, ck_b, ck,
                                                           NROWS, NH * KSZ, AHN);
    ck_softmax_kernel<<<(NROWS * NH + 255) / 256, 256>>>(ck);
    conv_out_kernel<<<NROWS, AHN>>>(co, ck, out);

    tdsm_kernel<<<BB, 256>>>(td, mask, tdsm);
    attn_kernel<<<dim3(SS / TI, NH, BB), 256, attn_smem>>>(mq, mk, mv, mask, tdsm,
                                                           gammas, out);
}